// round 13
// baseline (speedup 1.0000x reference)
#include <cuda_runtime.h>
#include <cuda_fp16.h>
#include <cstdint>
#include <cmath>

// ---------------- device scratch (no cudaMalloc allowed) -------------------
__device__ __align__(256) __half g_Xh[(size_t)8192*2048];      // Xcat fp16
__device__ __align__(256) __half g_Gh[(size_t)8*256*2048];     // G rows (m,h) x K=2048
__device__ __align__(256) __half g_Hidh[(size_t)8192*2048];    // hid fp16
__device__ __align__(256) __half g_B2h[8*512*256];             // [m][ W2 rows | F rows ]
__device__ __align__(256) __half g_Rqh[8192*256];
__device__ __align__(256) __half g_Wc1h[256*512];
__device__ __align__(256) __half g_Woh[(size_t)64*65536];      // Wo fp16
__device__ __align__(256) __half g_WvTh[(size_t)64*65536];     // Wv^T fp16
__device__ __align__(256) __half g_EfTh[(size_t)8*2048*256];   // EfT fp16
__device__ __align__(256) __half g_W1h[8*256*512];             // W1 fp16 (full)
__device__ __align__(256) __half g_W2Th[8*256*256];            // W2^T fp16
__device__ __align__(256) float g_fused[(size_t)8*8192*256];
__device__ __align__(256) float g_qpart[8192*256];
__device__ __align__(256) float g_bias1p[2048];
__device__ __align__(256) float g_bias2c[8*512];
__device__ __align__(256) float g_scorep[(size_t)8*8192*2];

// ---------------- helpers --------------------------------------------------
__device__ __forceinline__ uint32_t smem_u32(const void* p){
    uint32_t a; asm("{ .reg .u64 t; cvta.to.shared.u64 t, %1; cvt.u32.u64 %0, t; }":"=r"(a):"l"(p)); return a;
}
__device__ __forceinline__ void cp16(uint32_t d, const void* s){
    asm volatile("cp.async.cg.shared.global [%0], [%1], 16;"::"r"(d),"l"(s));
}
__device__ __forceinline__ void ldsm4(uint32_t&r0,uint32_t&r1,uint32_t&r2,uint32_t&r3,uint32_t a){
    asm volatile("ldmatrix.sync.aligned.m8n8.x4.shared.b16 {%0,%1,%2,%3}, [%4];"
        : "=r"(r0),"=r"(r1),"=r"(r2),"=r"(r3) : "r"(a));
}
__device__ __forceinline__ void mma_fp(float* c, const uint32_t* a, uint32_t b0, uint32_t b1){
    asm volatile("mma.sync.aligned.m16n8k16.row.col.f32.f16.f16.f32 "
        "{%0,%1,%2,%3}, {%4,%5,%6,%7}, {%8,%9}, {%0,%1,%2,%3};"
        : "+f"(c[0]),"+f"(c[1]),"+f"(c[2]),"+f"(c[3])
        : "r"(a[0]),"r"(a[1]),"r"(a[2]),"r"(a[3]),"r"(b0),"r"(b1));
}

// ====== fp16 NT GEMM v2: 256 thr, BM=128 BN=128 BK=64, 3-stage, 2 CTA/SM ====
// warp grid 2(M) x 4(N); warp tile 64 x 32.
// mode 0: out16 = relu(acc*aeff + bias)                       (hid)
// mode 1: outF  = acc + bias                                  (qpart)
// mode 2: x<2 -> outF (fused); x>=2 -> score epilogue
// mode 3: out16 = acc*aeff (+bias if given), no relu          (E/G/F builds)
//   out16 offset = zq*obA16 + zr*obB16  (zq=z/zdiv, zr=z%zdiv)
#define STV2 32768
#define SMEMV2 (3*STV2)
__global__ void __launch_bounds__(256,2) mma_fp16_v2(
    const __half* __restrict__ A, long aBatch, int ldA,
    const __half* __restrict__ B, long bBatch, int ldB, int K,
    const float* __restrict__ bias, long biasBatch,
    const float* __restrict__ addMat, int mode,
    float alpha, int diagMode, int zdiv,
    __half* __restrict__ out16, int ld16, long obA16, long obB16,
    float* __restrict__ outF, long obF, int ldF,
    const float* __restrict__ wc2, float* __restrict__ scoreOut)
{
    extern __shared__ __half sm2[];
    int tid = threadIdx.x, wid = tid>>5, lane = tid&31;
    int z = blockIdx.z;
    int zq = z/zdiv, zr = z - zq*zdiv;
    float aeff = (diagMode && zq==zr) ? 0.f : alpha;
    int row0 = blockIdx.y*128, col0 = blockIdx.x*128;
    const __half* Ap = A + (size_t)z*aBatch;
    const __half* Bp = B + (size_t)z*bBatch;
    const float* biasp = bias ? bias + (size_t)z*biasBatch : nullptr;
    int warpM = wid>>2, warpN = wid&3;
    float acc[4][4][4];
#pragma unroll
    for (int i=0;i<4;i++)
#pragma unroll
        for (int j=0;j<4;j++)
#pragma unroll
            for (int k=0;k<4;k++) acc[i][j][k]=0.f;

    uint32_t sb = smem_u32(sm2);
    int NK = K >> 6;

    auto load_chunk = [&](int kc, int bufi){
        uint32_t base = sb + bufi*STV2;
        int k0 = kc<<6;
#pragma unroll
        for (int it=0; it<4; it++){                 // A: 128 rows x 128B
            int idx = it*256 + tid;
            int row = idx>>3, j = idx&7;
            uint32_t dst = base + row*128 + ((j ^ (row&7))<<4);
            cp16(dst, Ap + (size_t)(row0+row)*ldA + k0 + j*8);
        }
#pragma unroll
        for (int it=0; it<4; it++){                 // B: 128 rows x 128B
            int idx = it*256 + tid;
            int row = idx>>3, j = idx&7;
            uint32_t dst = base + 16384 + row*128 + ((j ^ (row&7))<<4);
            cp16(dst, Bp + (size_t)(col0+row)*ldB + k0 + j*8);
        }
        asm volatile("cp.async.commit_group;":::"memory");
    };

    auto compute = [&](int bufi){
        uint32_t base = sb + bufi*STV2;
#pragma unroll
        for (int kk=0; kk<4; kk++){
            uint32_t ah[4][4];
#pragma unroll
            for (int mi=0;mi<4;mi++){
                int r = warpM*64 + mi*16 + (lane&15);
                int ce = kk*16 + ((lane>>4)<<3);
                uint32_t ad = base + r*128 + ((((ce>>3) ^ (r&7)))<<4);
                ldsm4(ah[mi][0],ah[mi][1],ah[mi][2],ah[mi][3], ad);
            }
#pragma unroll
            for (int np=0;np<2;np++){
                int g = lane>>3;
                int row = warpN*32 + np*16 + ((g&2)<<2) + (lane&7);
                int ce = kk*16 + ((g&1)<<3);
                uint32_t ad = base + 16384 + row*128 + ((((ce>>3) ^ (row&7)))<<4);
                uint32_t b0,b1,b2,b3;
                ldsm4(b0,b1,b2,b3, ad);
#pragma unroll
                for (int mi=0;mi<4;mi++){
                    mma_fp(acc[mi][2*np],   ah[mi], b0, b1);
                    mma_fp(acc[mi][2*np+1], ah[mi], b2, b3);
                }
            }
        }
    };

    load_chunk(0,0);
    if (NK > 1) load_chunk(1,1);
    int buf = 0;
    for (int kc=0; kc<NK; kc++){
        if (kc+1 < NK) asm volatile("cp.async.wait_group 1;":::"memory");
        else           asm volatile("cp.async.wait_group 0;":::"memory");
        __syncthreads();
        if (kc+2 < NK){
            int nb = buf+2; if (nb>=3) nb-=3;
            load_chunk(kc+2, nb);
        }
        compute(buf);
        if (++buf == 3) buf = 0;
    }

    // ---- epilogue ----
    int rb = row0 + warpM*64 + (lane>>2);
    int cb = col0 + warpN*32 + (lane&3)*2;
    bool scoreMode = (mode==2) && (blockIdx.x >= 2);
    size_t o16base = (size_t)zq*obA16 + (size_t)zr*obB16;
    float sacc[8];
#pragma unroll
    for (int k=0;k<8;k++) sacc[k]=0.f;
#pragma unroll
    for (int mi=0;mi<4;mi++){
        int r0 = rb + mi*16, r1 = r0 + 8;
#pragma unroll
        for (int ni=0;ni<4;ni++){
            int c = cb + ni*8;
            float b0 = 0.f, b1 = 0.f;
            if (biasp){ b0 = biasp[c]; b1 = biasp[c+1]; }
            float v0 = acc[mi][ni][0]*aeff+b0, v1 = acc[mi][ni][1]*aeff+b1;
            float v2 = acc[mi][ni][2]*aeff+b0, v3 = acc[mi][ni][3]*aeff+b1;
            if (scoreMode){
                int cc = c - 256;
                float2 a0 = *reinterpret_cast<const float2*>(addMat + (size_t)r0*256 + cc);
                float2 a1 = *reinterpret_cast<const float2*>(addMat + (size_t)r1*256 + cc);
                v0 = fmaxf(v0+a0.x, 0.f); v1 = fmaxf(v1+a0.y, 0.f);
                v2 = fmaxf(v2+a1.x, 0.f); v3 = fmaxf(v3+a1.y, 0.f);
                float w0 = wc2[cc], w1 = wc2[cc+1];
                sacc[mi*2+0] += v0*w0 + v1*w1;
                sacc[mi*2+1] += v2*w0 + v3*w1;
            } else if (mode==0 || mode==3){
                if (mode==0){
                    v0 = fmaxf(v0,0.f); v1 = fmaxf(v1,0.f);
                    v2 = fmaxf(v2,0.f); v3 = fmaxf(v3,0.f);
                }
                __half* o = out16 + o16base;
                *reinterpret_cast<__half2*>(o + (size_t)r0*ld16 + c) = __floats2half2_rn(v0,v1);
                *reinterpret_cast<__half2*>(o + (size_t)r1*ld16 + c) = __floats2half2_rn(v2,v3);
            } else {
                float* o = outF + (size_t)z*obF;
                *reinterpret_cast<float2*>(o + (size_t)r0*ldF + c) = make_float2(v0,v1);
                *reinterpret_cast<float2*>(o + (size_t)r1*ldF + c) = make_float2(v2,v3);
            }
        }
    }
    if (scoreMode){
#pragma unroll
        for (int k=0;k<8;k++){
            sacc[k] += __shfl_xor_sync(0xffffffffu, sacc[k], 1);
            sacc[k] += __shfl_xor_sync(0xffffffffu, sacc[k], 2);
        }
        __syncthreads();
        float* sred = reinterpret_cast<float*>(sm2);
        if ((lane&3)==0){
#pragma unroll
            for (int k=0;k<8;k++){
                int rl = warpM*64 + (k>>1)*16 + (k&1)*8 + (lane>>2);
                sred[rl*4 + warpN] = sacc[k];
            }
        }
        __syncthreads();
        if (tid < 128){
            float p = sred[tid*4] + sred[tid*4+1] + sred[tid*4+2] + sred[tid*4+3];
            scoreOut[((size_t)z*8192 + row0 + tid)*2 + (blockIdx.x - 2)] = p;
        }
    }
}

// ---------------- prep kernels ----------------------------------------------
__global__ void conv_fp16(const float* __restrict__ s, __half* __restrict__ d, int n){
    int i = blockIdx.x*256 + threadIdx.x;
    if (i < n) d[i] = __float2half(s[i]);
}
// T[p][d][e] = fp16(S[p][e][d]) for z matrices of 256x256
__global__ void transpose_fp16(const float* __restrict__ S, __half* __restrict__ T){
    __shared__ float tile[32][33];
    int p = blockIdx.z;
    const float* src = S + (size_t)p*65536;
    int x0 = blockIdx.x*32, y0 = blockIdx.y*32;
    for (int j = threadIdx.y; j < 32; j += 8)
        tile[j][threadIdx.x] = src[(size_t)(y0+j)*256 + x0 + threadIdx.x];
    __syncthreads();
    for (int j = threadIdx.y; j < 32; j += 8)
        T[(size_t)p*65536 + (size_t)(x0+j)*256 + y0 + threadIdx.x] = __float2half(tile[threadIdx.x][j]);
}
__global__ void xcat_fp16(const float* __restrict__ x, __half* __restrict__ Xh){
    size_t i = (size_t)blockIdx.x*256 + threadIdx.x;   // 4,194,304 float4 units
    int d4 = (int)(i & 63); size_t r = i >> 6;
    int b = (int)(r & 8191); int t = (int)(r >> 13);
    float4 v = reinterpret_cast<const float4*>(x)[i];
    size_t o = ((size_t)b*2048 + t*256 + d4*4) >> 1;
    reinterpret_cast<__half2*>(Xh)[o]   = __floats2half2_rn(v.x, v.y);
    reinterpret_cast<__half2*>(Xh)[o+1] = __floats2half2_rn(v.z, v.w);
}
__global__ void cbias_bias1p(const float* __restrict__ Wo, const float* __restrict__ bv,
                             const float* __restrict__ bo, const float* __restrict__ W1,
                             const float* __restrict__ b1, float* __restrict__ bias1p){
    int m = blockIdx.x;
    int w = threadIdx.x>>5, lane = threadIdx.x&31;
    __shared__ float cb[256];
    for (int r=0;r<32;r++){
        int o = w*32 + r;
        float p = 0.f;
        for (int t=0;t<8;t++){
            if (t==m) continue;
            size_t zz = (size_t)(m*8 + t);
            const float* W = Wo + zz*65536 + (size_t)o*256;
            const float* bvp = bv + zz*256;
            float q = 0.f;
#pragma unroll
            for (int j=0;j<8;j++) q += W[lane + j*32]*bvp[lane + j*32];
            p += q;
        }
#pragma unroll
        for (int off=16; off; off>>=1) p += __shfl_xor_sync(0xffffffffu, p, off);
        if (lane==0){
            float bs = 0.f;
            for (int t=0;t<8;t++) if (t!=m) bs += bo[(m*8+t)*256 + o];
            cb[o] = (p + bs) * (1.f/7.f);
        }
    }
    __syncthreads();
    for (int r=0;r<32;r++){
        int h = w*32 + r;
        float p = 0.f;
#pragma unroll
        for (int j=0;j<8;j++)
            p += W1[(size_t)m*131072 + (size_t)h*512 + 256 + lane + j*32] * cb[lane + j*32];
#pragma unroll
        for (int off=16; off; off>>=1) p += __shfl_xor_sync(0xffffffffu, p, off);
        if (lane==0) bias1p[m*256 + h] = p + b1[m*256 + h];
    }
}
__global__ void w2_to_b2_fp16(const float* __restrict__ W2, __half* __restrict__ B2h){
    int i = blockIdx.x*256 + threadIdx.x;       // 524288
    int m = i>>16, rem = i&65535;
    B2h[(size_t)m*131072 + rem] = __float2half(W2[i]);
}
__global__ void biasF_bias2c(const float* __restrict__ Wc1, const float* __restrict__ b2,
                             float* __restrict__ bias2c){
    int m = blockIdx.x;
    int w = threadIdx.x>>5, lane = threadIdx.x&31;
    __shared__ float bf[256];
    for (int r=0;r<32;r++){
        int d = w*32 + r;
        float p = 0.f;
#pragma unroll
        for (int j=0;j<8;j++)
            p += Wc1[(size_t)d*512 + 256 + lane + j*32] * b2[m*256 + lane + j*32];
#pragma unroll
        for (int off=16; off; off>>=1) p += __shfl_xor_sync(0xffffffffu, p, off);
        if (lane==0) bf[d] = p;
    }
    __syncthreads();
    bias2c[m*512 + threadIdx.x] = b2[m*256 + threadIdx.x];
    bias2c[m*512 + 256 + threadIdx.x] = bf[threadIdx.x];
}
__global__ void g_patch_fp16(const float* __restrict__ W1, __half* __restrict__ Gh){
    int i = blockIdx.x*256 + threadIdx.x;       // 524288
    int m = i>>16, rem = i&65535, h = rem>>8, d = rem&255;
    Gh[(size_t)m*524288 + (size_t)h*2048 + m*256 + d] =
        __float2half(W1[(size_t)m*131072 + (size_t)h*512 + d]);
}
__global__ void final_gate(const float* __restrict__ scorep, const float* __restrict__ fused,
                           const float* __restrict__ bc2, float* __restrict__ out){
    int b = blockIdx.x, tid = threadIdx.x;
    __shared__ float ssc[8];
    if (tid < 8){
        size_t i = ((size_t)tid*8192 + b)*2;
        float p = scorep[i] + scorep[i+1];
        ssc[tid] = 1.f/(1.f + expf(-(p + bc2[0])));
    }
    __syncthreads();
    float a = 0.f;
#pragma unroll
    for (int m=0;m<8;m++)
        a += ssc[m]*fused[((size_t)m*8192 + b)*256 + tid];
    out[(size_t)b*256 + tid] = a*0.125f;
}

// ---------------- launch ----------------------------------------------------
extern "C" void kernel_launch(void* const* d_in, const int* in_sizes, int n_in,
                              void* d_out, int out_size) {
    const float* x   = (const float*)d_in[0];
    const float* rq  = (const float*)d_in[1];
    const float* Wv  = (const float*)d_in[2];
    const float* bv  = (const float*)d_in[3];
    const float* Wo  = (const float*)d_in[4];
    const float* bo  = (const float*)d_in[5];
    const float* W1  = (const float*)d_in[6];
    const float* b1  = (const float*)d_in[7];
    const float* W2  = (const float*)d_in[8];
    const float* b2  = (const float*)d_in[9];
    const float* Wc1 = (const float*)d_in[10];
    const float* bc1 = (const float*)d_in[11];
    const float* wc2 = (const float*)d_in[12];
    const float* bc2 = (const float*)d_in[13];
    float* out = (float*)d_out;

    __half *pXh,*pGh,*pHh,*pB2h,*pRqh,*pWc1h,*pWoh,*pWvTh,*pEfTh,*pW1h,*pW2Th;
    float *pfused,*pqpart,*pbias1p,*pbias2c,*pscorep;
    cudaGetSymbolAddress((void**)&pXh, g_Xh);      cudaGetSymbolAddress((void**)&pGh, g_Gh);
    cudaGetSymbolAddress((void**)&pHh, g_Hidh);    cudaGetSymbolAddress((void**)&pB2h, g_B2h);
    cudaGetSymbolAddress((void**)&pRqh, g_Rqh);    cudaGetSymbolAddress((void**)&pWc1h, g_Wc1h);
    cudaGetSymbolAddress((void**)&pWoh, g_Woh);    cudaGetSymbolAddress((void**)&pWvTh, g_WvTh);
    cudaGetSymbolAddress((void**)&pEfTh, g_EfTh);  cudaGetSymbolAddress((void**)&pW1h, g_W1h);
    cudaGetSymbolAddress((void**)&pW2Th, g_W2Th);
    cudaGetSymbolAddress((void**)&pfused, g_fused);
    cudaGetSymbolAddress((void**)&pqpart, g_qpart);
    cudaGetSymbolAddress((void**)&pbias1p, g_bias1p);
    cudaGetSymbolAddress((void**)&pbias2c, g_bias2c);
    cudaGetSymbolAddress((void**)&pscorep, g_scorep);
    cudaFuncSetAttribute(mma_fp16_v2, cudaFuncAttributeMaxDynamicSharedMemorySize, SMEMV2);

    conv_fp16<<<16384, 256>>>(Wo, pWoh, 4194304);                           // 1
    transpose_fp16<<<dim3(8,8,64), dim3(32,8)>>>(Wv, pWvTh);                // 2
    xcat_fp16<<<16384, 256>>>(x, pXh);                                      // 3
    // 4: EfT[s][(t,d)][o] = (s!=t)/7 * sum_e WvT[s,t][d,e]*Wo[s,t][o,e]  (ncu target)
    mma_fp16_v2<<<dim3(2,2,64), 256, SMEMV2>>>(
        pWvTh, 65536, 256,  pWoh, 65536, 256,  256,
        nullptr, 0,  nullptr, 3,
        1.f/7.f, 1, 8,
        pEfTh, 256, 524288, 65536,
        nullptr, 0, 0,
        nullptr, nullptr);
    conv_fp16<<<8192, 256>>>(rq, pRqh, 2097152);                            // 5
    conv_fp16<<<512, 256>>>(Wc1, pWc1h, 131072);                            // 6
    conv_fp16<<<4096, 256>>>(W1, pW1h, 1048576);                            // 7
    cbias_bias1p<<<8, 256>>>(Wo, bv, bo, W1, b1, pbias1p);                  // 8
    transpose_fp16<<<dim3(8,8,8), dim3(32,8)>>>(W2, pW2Th);                 // 9
    w2_to_b2_fp16<<<2048, 256>>>(W2, pB2h);                                 // 10
    biasF_bias2c<<<8, 256>>>(Wc1, b2, pbias2c);                             // 11
    // 12: G[m][h][td] = sum_o W1c[m][h,o]*EfT[m][(td)][o]  -> fp16
    mma_fp16_v2<<<dim3(16,2,8), 256, SMEMV2>>>(
        pW1h + 256, 131072, 512,  pEfTh, 524288, 256,  256,
        nullptr, 0,  nullptr, 3,
        1.f, 0, 1,
        pGh, 2048, 524288, 0,
        nullptr, 0, 0,
        nullptr, nullptr);
    g_patch_fp16<<<2048, 256>>>(W1, pGh);                                   // 13
    // 14: F[m][d][h] = sum_o Wc1c[d,o]*W2T[m][h,o] -> fp16 into B2 rows 256-511
    mma_fp16_v2<<<dim3(2,2,8), 256, SMEMV2>>>(
        pWc1h + 256, 0, 512,  pW2Th, 65536, 256,  256,
        nullptr, 0,  nullptr, 3,
        1.f, 0, 1,
        pB2h + 65536, 256, 131072, 0,
        nullptr, 0, 0,
        nullptr, nullptr);
    // 15: qpart = rq @ Wc1[:, :256]^T + bc1 (fp32)
    mma_fp16_v2<<<dim3(2,64,1), 256, SMEMV2>>>(
        pRqh, 0, 256,  pWc1h, 0, 512,  256,
        bc1, 0,  nullptr, 1,
        1.f, 0, 1,
        nullptr, 0, 0, 0,
        pqpart, 0, 256,
        nullptr, nullptr);
    // 16: hid_all = relu(Xh @ Gh^T + bias1p)  [8192x2048, K=2048] -> fp16
    mma_fp16_v2<<<dim3(16,64,1), 256, SMEMV2>>>(
        pXh, 0, 2048,  pGh, 0, 2048,  2048,
        pbias1p, 0,  nullptr, 0,
        1.f, 0, 1,
        pHh, 2048, 0, 0,
        nullptr, 0, 0,
        nullptr, nullptr);
    // 17: fused (x=0,1 -> fp32 cols 0-255) + score (x=2,3 -> slots 0,1)
    mma_fp16_v2<<<dim3(4,64,8), 256, SMEMV2>>>(
        pHh, 256, 2048,  pB2h, 131072, 256,  256,
        pbias2c, 512,  pqpart, 2,
        1.f, 0, 1,
        nullptr, 0, 0, 0,
        pfused, 2097152, 256,
        wc2, pscorep);
    // 18
    final_gate<<<8192, 256>>>(pscorep, pfused, bc2, out);
}

// round 14
// speedup vs baseline: 1.4140x; 1.4140x over previous
#include <cuda_runtime.h>
#include <cuda_fp16.h>
#include <cstdint>
#include <cmath>

// ---------------- device scratch (no cudaMalloc allowed) -------------------
__device__ __align__(256) __half g_Xh[(size_t)8192*2048];      // Xcat fp16
__device__ __align__(256) __half g_Gh[(size_t)8*256*2048];     // G rows (m,h) x K=2048
__device__ __align__(256) __half g_Hidh[(size_t)8192*2048];    // hid fp16
__device__ __align__(256) __half g_B2h[8*512*256];             // [m][ W2 rows | F rows ]
__device__ __align__(256) __half g_Rqh[8192*256];
__device__ __align__(256) __half g_Wc1h[256*512];
__device__ __align__(256) __half g_Woh[(size_t)64*65536];      // Wo fp16
__device__ __align__(256) __half g_WvTh[(size_t)64*65536];     // Wv^T fp16
__device__ __align__(256) __half g_EfTh[(size_t)8*2048*256];   // EfT fp16
__device__ __align__(256) __half g_W1h[8*256*512];             // W1 fp16 (full)
__device__ __align__(256) __half g_W2Th[8*256*256];            // W2^T fp16
__device__ __align__(256) float g_fused[(size_t)8*8192*256];
__device__ __align__(256) float g_qpart[8192*256];
__device__ __align__(256) float g_bias1p[2048];
__device__ __align__(256) float g_bias2c[8*512];
__device__ __align__(256) float g_scorep[(size_t)8*8192*2];

// ---------------- helpers --------------------------------------------------
__device__ __forceinline__ uint32_t smem_u32(const void* p){
    uint32_t a; asm("{ .reg .u64 t; cvta.to.shared.u64 t, %1; cvt.u32.u64 %0, t; }":"=r"(a):"l"(p)); return a;
}
__device__ __forceinline__ void cp16(uint32_t d, const void* s){
    asm volatile("cp.async.cg.shared.global [%0], [%1], 16;"::"r"(d),"l"(s));
}
__device__ __forceinline__ void ldsm4(uint32_t&r0,uint32_t&r1,uint32_t&r2,uint32_t&r3,uint32_t a){
    asm volatile("ldmatrix.sync.aligned.m8n8.x4.shared.b16 {%0,%1,%2,%3}, [%4];"
        : "=r"(r0),"=r"(r1),"=r"(r2),"=r"(r3) : "r"(a));
}
__device__ __forceinline__ void mma_fp(float* c, const uint32_t* a, uint32_t b0, uint32_t b1){
    asm volatile("mma.sync.aligned.m16n8k16.row.col.f32.f16.f16.f32 "
        "{%0,%1,%2,%3}, {%4,%5,%6,%7}, {%8,%9}, {%0,%1,%2,%3};"
        : "+f"(c[0]),"+f"(c[1]),"+f"(c[2]),"+f"(c[3])
        : "r"(a[0]),"r"(a[1]),"r"(a[2]),"r"(a[3]),"r"(b0),"r"(b1));
}

// ====== fp16 NT GEMM v2: 256 thr, BM=128 BN=128 BK=64, 3-stage, 2 CTA/SM ====
// Templated MODE keeps the hot instantiations (0, 2) at R12 register pressure.
// MODE 0: out16 = relu(acc + bias)                       (hid)
// MODE 1: outF  = acc + bias                             (qpart)
// MODE 2: x<2 -> outF (fused); x>=2 -> score epilogue
// MODE 3: out16[zq*obA16 + zr*obB16] = acc*aeff          (E/G/F weight builds)
#define STV2 32768
#define SMEMV2 (3*STV2)
template<int MODE>
__global__ void __launch_bounds__(256,2) mma_fp16_v2(
    const __half* __restrict__ A, long aBatch, int ldA,
    const __half* __restrict__ B, long bBatch, int ldB, int K,
    const float* __restrict__ bias, long biasBatch,
    const float* __restrict__ addMat,
    float alpha, int diagMode, int zdiv,
    __half* __restrict__ out16, int ld16, long obA16, long obB16,
    float* __restrict__ outF, long obF, int ldF,
    const float* __restrict__ wc2, float* __restrict__ scoreOut)
{
    extern __shared__ __half sm2[];
    int tid = threadIdx.x, wid = tid>>5, lane = tid&31;
    int z = blockIdx.z;
    int row0 = blockIdx.y*128, col0 = blockIdx.x*128;
    const __half* Ap = A + (size_t)z*aBatch;
    const __half* Bp = B + (size_t)z*bBatch;
    int warpM = wid>>2, warpN = wid&3;
    float acc[4][4][4];
#pragma unroll
    for (int i=0;i<4;i++)
#pragma unroll
        for (int j=0;j<4;j++)
#pragma unroll
            for (int k=0;k<4;k++) acc[i][j][k]=0.f;

    uint32_t sb = smem_u32(sm2);
    int NK = K >> 6;

    auto load_chunk = [&](int kc, int bufi){
        uint32_t base = sb + bufi*STV2;
        int k0 = kc<<6;
#pragma unroll
        for (int it=0; it<4; it++){                 // A: 128 rows x 128B
            int idx = it*256 + tid;
            int row = idx>>3, j = idx&7;
            uint32_t dst = base + row*128 + ((j ^ (row&7))<<4);
            cp16(dst, Ap + (size_t)(row0+row)*ldA + k0 + j*8);
        }
#pragma unroll
        for (int it=0; it<4; it++){                 // B: 128 rows x 128B
            int idx = it*256 + tid;
            int row = idx>>3, j = idx&7;
            uint32_t dst = base + 16384 + row*128 + ((j ^ (row&7))<<4);
            cp16(dst, Bp + (size_t)(col0+row)*ldB + k0 + j*8);
        }
        asm volatile("cp.async.commit_group;":::"memory");
    };

    auto compute = [&](int bufi){
        uint32_t base = sb + bufi*STV2;
#pragma unroll
        for (int kk=0; kk<4; kk++){
            uint32_t ah[4][4];
#pragma unroll
            for (int mi=0;mi<4;mi++){
                int r = warpM*64 + mi*16 + (lane&15);
                int ce = kk*16 + ((lane>>4)<<3);
                uint32_t ad = base + r*128 + ((((ce>>3) ^ (r&7)))<<4);
                ldsm4(ah[mi][0],ah[mi][1],ah[mi][2],ah[mi][3], ad);
            }
#pragma unroll
            for (int np=0;np<2;np++){
                int g = lane>>3;
                int row = warpN*32 + np*16 + ((g&2)<<2) + (lane&7);
                int ce = kk*16 + ((g&1)<<3);
                uint32_t ad = base + 16384 + row*128 + ((((ce>>3) ^ (row&7)))<<4);
                uint32_t b0,b1,b2,b3;
                ldsm4(b0,b1,b2,b3, ad);
#pragma unroll
                for (int mi=0;mi<4;mi++){
                    mma_fp(acc[mi][2*np],   ah[mi], b0, b1);
                    mma_fp(acc[mi][2*np+1], ah[mi], b2, b3);
                }
            }
        }
    };

    load_chunk(0,0);
    if (NK > 1) load_chunk(1,1);
    int buf = 0;
    for (int kc=0; kc<NK; kc++){
        if (kc+1 < NK) asm volatile("cp.async.wait_group 1;":::"memory");
        else           asm volatile("cp.async.wait_group 0;":::"memory");
        __syncthreads();
        if (kc+2 < NK){
            int nb = buf+2; if (nb>=3) nb-=3;
            load_chunk(kc+2, nb);
        }
        compute(buf);
        if (++buf == 3) buf = 0;
    }

    // ---- epilogue (per-MODE via if constexpr) ----
    int rb = row0 + warpM*64 + (lane>>2);
    int cb = col0 + warpN*32 + (lane&3)*2;

    if constexpr (MODE == 3){
        int zq = z/zdiv, zr = z - zq*zdiv;
        float aeff = (diagMode && zq == zr) ? 0.f : alpha;
        __half* o = out16 + (size_t)zq*obA16 + (size_t)zr*obB16;
#pragma unroll
        for (int mi=0;mi<4;mi++){
            int r0 = rb + mi*16, r1 = r0 + 8;
#pragma unroll
            for (int ni=0;ni<4;ni++){
                int c = cb + ni*8;
                *reinterpret_cast<__half2*>(o + (size_t)r0*ld16 + c) =
                    __floats2half2_rn(acc[mi][ni][0]*aeff, acc[mi][ni][1]*aeff);
                *reinterpret_cast<__half2*>(o + (size_t)r1*ld16 + c) =
                    __floats2half2_rn(acc[mi][ni][2]*aeff, acc[mi][ni][3]*aeff);
            }
        }
    } else if constexpr (MODE == 0){
        const float* biasp = bias;
#pragma unroll
        for (int mi=0;mi<4;mi++){
            int r0 = rb + mi*16, r1 = r0 + 8;
#pragma unroll
            for (int ni=0;ni<4;ni++){
                int c = cb + ni*8;
                float b0 = biasp[c], b1 = biasp[c+1];
                float v0 = fmaxf(acc[mi][ni][0]+b0, 0.f), v1 = fmaxf(acc[mi][ni][1]+b1, 0.f);
                float v2 = fmaxf(acc[mi][ni][2]+b0, 0.f), v3 = fmaxf(acc[mi][ni][3]+b1, 0.f);
                *reinterpret_cast<__half2*>(out16 + (size_t)r0*ld16 + c) = __floats2half2_rn(v0,v1);
                *reinterpret_cast<__half2*>(out16 + (size_t)r1*ld16 + c) = __floats2half2_rn(v2,v3);
            }
        }
    } else if constexpr (MODE == 1){
        const float* biasp = bias;
#pragma unroll
        for (int mi=0;mi<4;mi++){
            int r0 = rb + mi*16, r1 = r0 + 8;
#pragma unroll
            for (int ni=0;ni<4;ni++){
                int c = cb + ni*8;
                float b0 = biasp[c], b1 = biasp[c+1];
                *reinterpret_cast<float2*>(outF + (size_t)r0*ldF + c) =
                    make_float2(acc[mi][ni][0]+b0, acc[mi][ni][1]+b1);
                *reinterpret_cast<float2*>(outF + (size_t)r1*ldF + c) =
                    make_float2(acc[mi][ni][2]+b0, acc[mi][ni][3]+b1);
            }
        }
    } else { // MODE == 2
        const float* biasp = bias + (size_t)z*biasBatch;
        bool scoreMode = (blockIdx.x >= 2);
        float sacc[8];
#pragma unroll
        for (int k=0;k<8;k++) sacc[k]=0.f;
#pragma unroll
        for (int mi=0;mi<4;mi++){
            int r0 = rb + mi*16, r1 = r0 + 8;
#pragma unroll
            for (int ni=0;ni<4;ni++){
                int c = cb + ni*8;
                float b0 = biasp[c], b1 = biasp[c+1];
                float v0 = acc[mi][ni][0]+b0, v1 = acc[mi][ni][1]+b1;
                float v2 = acc[mi][ni][2]+b0, v3 = acc[mi][ni][3]+b1;
                if (scoreMode){
                    int cc = c - 256;
                    float2 a0 = *reinterpret_cast<const float2*>(addMat + (size_t)r0*256 + cc);
                    float2 a1 = *reinterpret_cast<const float2*>(addMat + (size_t)r1*256 + cc);
                    v0 = fmaxf(v0+a0.x, 0.f); v1 = fmaxf(v1+a0.y, 0.f);
                    v2 = fmaxf(v2+a1.x, 0.f); v3 = fmaxf(v3+a1.y, 0.f);
                    float w0 = wc2[cc], w1 = wc2[cc+1];
                    sacc[mi*2+0] += v0*w0 + v1*w1;
                    sacc[mi*2+1] += v2*w0 + v3*w1;
                } else {
                    float* o = outF + (size_t)z*obF;
                    *reinterpret_cast<float2*>(o + (size_t)r0*ldF + c) = make_float2(v0,v1);
                    *reinterpret_cast<float2*>(o + (size_t)r1*ldF + c) = make_float2(v2,v3);
                }
            }
        }
        if (scoreMode){
#pragma unroll
            for (int k=0;k<8;k++){
                sacc[k] += __shfl_xor_sync(0xffffffffu, sacc[k], 1);
                sacc[k] += __shfl_xor_sync(0xffffffffu, sacc[k], 2);
            }
            __syncthreads();
            float* sred = reinterpret_cast<float*>(sm2);
            if ((lane&3)==0){
#pragma unroll
                for (int k=0;k<8;k++){
                    int rl = warpM*64 + (k>>1)*16 + (k&1)*8 + (lane>>2);
                    sred[rl*4 + warpN] = sacc[k];
                }
            }
            __syncthreads();
            if (tid < 128){
                float p = sred[tid*4] + sred[tid*4+1] + sred[tid*4+2] + sred[tid*4+3];
                scoreOut[((size_t)z*8192 + row0 + tid)*2 + (blockIdx.x - 2)] = p;
            }
        }
    }
}

// ---------------- prep kernels ----------------------------------------------
__global__ void conv_fp16(const float* __restrict__ s, __half* __restrict__ d, int n){
    int i = blockIdx.x*256 + threadIdx.x;
    if (i < n) d[i] = __float2half(s[i]);
}
__global__ void transpose_fp16(const float* __restrict__ S, __half* __restrict__ T){
    __shared__ float tile[32][33];
    int p = blockIdx.z;
    const float* src = S + (size_t)p*65536;
    int x0 = blockIdx.x*32, y0 = blockIdx.y*32;
    for (int j = threadIdx.y; j < 32; j += 8)
        tile[j][threadIdx.x] = src[(size_t)(y0+j)*256 + x0 + threadIdx.x];
    __syncthreads();
    for (int j = threadIdx.y; j < 32; j += 8)
        T[(size_t)p*65536 + (size_t)(x0+j)*256 + y0 + threadIdx.x] = __float2half(tile[threadIdx.x][j]);
}
__global__ void xcat_fp16(const float* __restrict__ x, __half* __restrict__ Xh){
    size_t i = (size_t)blockIdx.x*256 + threadIdx.x;   // 4,194,304 float4 units
    int d4 = (int)(i & 63); size_t r = i >> 6;
    int b = (int)(r & 8191); int t = (int)(r >> 13);
    float4 v = reinterpret_cast<const float4*>(x)[i];
    size_t o = ((size_t)b*2048 + t*256 + d4*4) >> 1;
    reinterpret_cast<__half2*>(Xh)[o]   = __floats2half2_rn(v.x, v.y);
    reinterpret_cast<__half2*>(Xh)[o+1] = __floats2half2_rn(v.z, v.w);
}
__global__ void cbias_bias1p(const float* __restrict__ Wo, const float* __restrict__ bv,
                             const float* __restrict__ bo, const float* __restrict__ W1,
                             const float* __restrict__ b1, float* __restrict__ bias1p){
    int m = blockIdx.x;
    int w = threadIdx.x>>5, lane = threadIdx.x&31;
    __shared__ float cb[256];
    for (int r=0;r<32;r++){
        int o = w*32 + r;
        float p = 0.f;
        for (int t=0;t<8;t++){
            if (t==m) continue;
            size_t zz = (size_t)(m*8 + t);
            const float* W = Wo + zz*65536 + (size_t)o*256;
            const float* bvp = bv + zz*256;
            float q = 0.f;
#pragma unroll
            for (int j=0;j<8;j++) q += W[lane + j*32]*bvp[lane + j*32];
            p += q;
        }
#pragma unroll
        for (int off=16; off; off>>=1) p += __shfl_xor_sync(0xffffffffu, p, off);
        if (lane==0){
            float bs = 0.f;
            for (int t=0;t<8;t++) if (t!=m) bs += bo[(m*8+t)*256 + o];
            cb[o] = (p + bs) * (1.f/7.f);
        }
    }
    __syncthreads();
    for (int r=0;r<32;r++){
        int h = w*32 + r;
        float p = 0.f;
#pragma unroll
        for (int j=0;j<8;j++)
            p += W1[(size_t)m*131072 + (size_t)h*512 + 256 + lane + j*32] * cb[lane + j*32];
#pragma unroll
        for (int off=16; off; off>>=1) p += __shfl_xor_sync(0xffffffffu, p, off);
        if (lane==0) bias1p[m*256 + h] = p + b1[m*256 + h];
    }
}
__global__ void w2_to_b2_fp16(const float* __restrict__ W2, __half* __restrict__ B2h){
    int i = blockIdx.x*256 + threadIdx.x;       // 524288
    int m = i>>16, rem = i&65535;
    B2h[(size_t)m*131072 + rem] = __float2half(W2[i]);
}
__global__ void biasF_bias2c(const float* __restrict__ Wc1, const float* __restrict__ b2,
                             float* __restrict__ bias2c){
    int m = blockIdx.x;
    int w = threadIdx.x>>5, lane = threadIdx.x&31;
    __shared__ float bf[256];
    for (int r=0;r<32;r++){
        int d = w*32 + r;
        float p = 0.f;
#pragma unroll
        for (int j=0;j<8;j++)
            p += Wc1[(size_t)d*512 + 256 + lane + j*32] * b2[m*256 + lane + j*32];
#pragma unroll
        for (int off=16; off; off>>=1) p += __shfl_xor_sync(0xffffffffu, p, off);
        if (lane==0) bf[d] = p;
    }
    __syncthreads();
    bias2c[m*512 + threadIdx.x] = b2[m*256 + threadIdx.x];
    bias2c[m*512 + 256 + threadIdx.x] = bf[threadIdx.x];
}
__global__ void g_patch_fp16(const float* __restrict__ W1, __half* __restrict__ Gh){
    int i = blockIdx.x*256 + threadIdx.x;       // 524288
    int m = i>>16, rem = i&65535, h = rem>>8, d = rem&255;
    Gh[(size_t)m*524288 + (size_t)h*2048 + m*256 + d] =
        __float2half(W1[(size_t)m*131072 + (size_t)h*512 + d]);
}
__global__ void final_gate(const float* __restrict__ scorep, const float* __restrict__ fused,
                           const float* __restrict__ bc2, float* __restrict__ out){
    int b = blockIdx.x, tid = threadIdx.x;
    __shared__ float ssc[8];
    if (tid < 8){
        size_t i = ((size_t)tid*8192 + b)*2;
        float p = scorep[i] + scorep[i+1];
        ssc[tid] = 1.f/(1.f + expf(-(p + bc2[0])));
    }
    __syncthreads();
    float a = 0.f;
#pragma unroll
    for (int m=0;m<8;m++)
        a += ssc[m]*fused[((size_t)m*8192 + b)*256 + tid];
    out[(size_t)b*256 + tid] = a*0.125f;
}

// ---------------- launch ----------------------------------------------------
extern "C" void kernel_launch(void* const* d_in, const int* in_sizes, int n_in,
                              void* d_out, int out_size) {
    const float* x   = (const float*)d_in[0];
    const float* rq  = (const float*)d_in[1];
    const float* Wv  = (const float*)d_in[2];
    const float* bv  = (const float*)d_in[3];
    const float* Wo  = (const float*)d_in[4];
    const float* bo  = (const float*)d_in[5];
    const float* W1  = (const float*)d_in[6];
    const float* b1  = (const float*)d_in[7];
    const float* W2  = (const float*)d_in[8];
    const float* b2  = (const float*)d_in[9];
    const float* Wc1 = (const float*)d_in[10];
    const float* bc1 = (const float*)d_in[11];
    const float* wc2 = (const float*)d_in[12];
    const float* bc2 = (const float*)d_in[13];
    float* out = (float*)d_out;

    __half *pXh,*pGh,*pHh,*pB2h,*pRqh,*pWc1h,*pWoh,*pWvTh,*pEfTh,*pW1h,*pW2Th;
    float *pfused,*pqpart,*pbias1p,*pbias2c,*pscorep;
    cudaGetSymbolAddress((void**)&pXh, g_Xh);      cudaGetSymbolAddress((void**)&pGh, g_Gh);
    cudaGetSymbolAddress((void**)&pHh, g_Hidh);    cudaGetSymbolAddress((void**)&pB2h, g_B2h);
    cudaGetSymbolAddress((void**)&pRqh, g_Rqh);    cudaGetSymbolAddress((void**)&pWc1h, g_Wc1h);
    cudaGetSymbolAddress((void**)&pWoh, g_Woh);    cudaGetSymbolAddress((void**)&pWvTh, g_WvTh);
    cudaGetSymbolAddress((void**)&pEfTh, g_EfTh);  cudaGetSymbolAddress((void**)&pW1h, g_W1h);
    cudaGetSymbolAddress((void**)&pW2Th, g_W2Th);
    cudaGetSymbolAddress((void**)&pfused, g_fused);
    cudaGetSymbolAddress((void**)&pqpart, g_qpart);
    cudaGetSymbolAddress((void**)&pbias1p, g_bias1p);
    cudaGetSymbolAddress((void**)&pbias2c, g_bias2c);
    cudaGetSymbolAddress((void**)&pscorep, g_scorep);
    cudaFuncSetAttribute(mma_fp16_v2<0>, cudaFuncAttributeMaxDynamicSharedMemorySize, SMEMV2);
    cudaFuncSetAttribute(mma_fp16_v2<1>, cudaFuncAttributeMaxDynamicSharedMemorySize, SMEMV2);
    cudaFuncSetAttribute(mma_fp16_v2<2>, cudaFuncAttributeMaxDynamicSharedMemorySize, SMEMV2);
    cudaFuncSetAttribute(mma_fp16_v2<3>, cudaFuncAttributeMaxDynamicSharedMemorySize, SMEMV2);

    conv_fp16<<<16384, 256>>>(Wo, pWoh, 4194304);                           // 1
    transpose_fp16<<<dim3(8,8,64), dim3(32,8)>>>(Wv, pWvTh);                // 2
    xcat_fp16<<<16384, 256>>>(x, pXh);                                      // 3
    // 4: EfT[s][(t,d)][o] = (s!=t)/7 * sum_e WvT[s,t][d,e]*Wo[s,t][o,e]  (ncu target)
    mma_fp16_v2<3><<<dim3(2,2,64), 256, SMEMV2>>>(
        pWvTh, 65536, 256,  pWoh, 65536, 256,  256,
        nullptr, 0,  nullptr,
        1.f/7.f, 1, 8,
        pEfTh, 256, 524288, 65536,
        nullptr, 0, 0,
        nullptr, nullptr);
    conv_fp16<<<8192, 256>>>(rq, pRqh, 2097152);                            // 5
    conv_fp16<<<512, 256>>>(Wc1, pWc1h, 131072);                            // 6
    conv_fp16<<<4096, 256>>>(W1, pW1h, 1048576);                            // 7
    cbias_bias1p<<<8, 256>>>(Wo, bv, bo, W1, b1, pbias1p);                  // 8
    transpose_fp16<<<dim3(8,8,8), dim3(32,8)>>>(W2, pW2Th);                 // 9
    w2_to_b2_fp16<<<2048, 256>>>(W2, pB2h);                                 // 10
    biasF_bias2c<<<8, 256>>>(Wc1, b2, pbias2c);                             // 11
    // 12: G[m][h][td] = sum_o W1c[m][h,o]*EfT[m][(td)][o]  -> fp16
    mma_fp16_v2<3><<<dim3(16,2,8), 256, SMEMV2>>>(
        pW1h + 256, 131072, 512,  pEfTh, 524288, 256,  256,
        nullptr, 0,  nullptr,
        1.f, 0, 1,
        pGh, 2048, 524288, 0,
        nullptr, 0, 0,
        nullptr, nullptr);
    g_patch_fp16<<<2048, 256>>>(W1, pGh);                                   // 13
    // 14: F[m][d][h] = sum_o Wc1c[d,o]*W2T[m][h,o] -> fp16 into B2 rows 256-511
    mma_fp16_v2<3><<<dim3(2,2,8), 256, SMEMV2>>>(
        pWc1h + 256, 0, 512,  pW2Th, 65536, 256,  256,
        nullptr, 0,  nullptr,
        1.f, 0, 1,
        pB2h + 65536, 256, 131072, 0,
        nullptr, 0, 0,
        nullptr, nullptr);
    // 15: qpart = rq @ Wc1[:, :256]^T + bc1 (fp32)
    mma_fp16_v2<1><<<dim3(2,64,1), 256, SMEMV2>>>(
        pRqh, 0, 256,  pWc1h, 0, 512,  256,
        bc1, 0,  nullptr,
        1.f, 0, 1,
        nullptr, 0, 0, 0,
        pqpart, 0, 256,
        nullptr, nullptr);
    // 16: hid_all = relu(Xh @ Gh^T + bias1p)  [8192x2048, K=2048] -> fp16
    mma_fp16_v2<0><<<dim3(16,64,1), 256, SMEMV2>>>(
        pXh, 0, 2048,  pGh, 0, 2048,  2048,
        pbias1p, 0,  nullptr,
        1.f, 0, 1,
        pHh, 2048, 0, 0,
        nullptr, 0, 0,
        nullptr, nullptr);
    // 17: fused (x=0,1 -> fp32 cols 0-255) + score (x=2,3 -> slots 0,1)
    mma_fp16_v2<2><<<dim3(4,64,8), 256, SMEMV2>>>(
        pHh, 256, 2048,  pB2h, 131072, 256,  256,
        pbias2c, 512,  pqpart,
        1.f, 0, 1,
        nullptr, 0, 0, 0,
        pfused, 2097152, 256,
        wc2, pscorep);
    // 18
    final_gate<<<8192, 256>>>(pscorep, pfused, bc2, out);
}

// round 15
// speedup vs baseline: 1.6994x; 1.2019x over previous
#include <cuda_runtime.h>
#include <cuda_bf16.h>
#include <cuda_fp16.h>
#include <cstdint>
#include <cmath>

using bf16 = __nv_bfloat16;

// ---------------- device scratch (no cudaMalloc allowed) -------------------
__device__ __align__(256) __half g_Xh[(size_t)8192*2048];      // Xcat fp16
__device__ __align__(256) __half g_Gh[(size_t)8*256*2048];     // G rows (m,h) x K=2048
__device__ __align__(256) __half g_Hidh[(size_t)8192*2048];    // hid fp16
__device__ __align__(256) __half g_B2h[8*512*256];             // [m][ W2 rows | F rows ]
__device__ __align__(256) __half g_Rqh[8192*256];
__device__ __align__(256) __half g_Wc1h[256*512];
__device__ __align__(256) float g_fused[(size_t)8*8192*256];
__device__ __align__(256) bf16 g_WoH[64*256*256];
__device__ __align__(256) bf16 g_WoL[64*256*256];
__device__ __align__(256) bf16 g_WvTH[64*256*256];
__device__ __align__(256) bf16 g_WvTL[64*256*256];
__device__ __align__(256) bf16 g_EfTH[8*2048*256];
__device__ __align__(256) bf16 g_EfTL[8*2048*256];
__device__ __align__(256) bf16 g_W1H[8*256*512];
__device__ __align__(256) bf16 g_W1L[8*256*512];
__device__ __align__(256) bf16 g_W2TH[8*256*256];
__device__ __align__(256) bf16 g_W2TL[8*256*256];
__device__ __align__(256) bf16 g_WcH[256*512];
__device__ __align__(256) bf16 g_WcL[256*512];
__device__ __align__(256) float g_qpart[8192*256];
__device__ __align__(256) float g_bias1p[2048];
__device__ __align__(256) float g_bias2c[8*512];
__device__ __align__(256) float g_scorep[(size_t)8*8192*2];

// ---------------- helpers --------------------------------------------------
__device__ __forceinline__ uint32_t smem_u32(const void* p){
    uint32_t a; asm("{ .reg .u64 t; cvta.to.shared.u64 t, %1; cvt.u32.u64 %0, t; }":"=r"(a):"l"(p)); return a;
}
__device__ __forceinline__ void cp16(uint32_t d, const void* s){
    asm volatile("cp.async.cg.shared.global [%0], [%1], 16;"::"r"(d),"l"(s));
}
__device__ __forceinline__ void ldsm4(uint32_t&r0,uint32_t&r1,uint32_t&r2,uint32_t&r3,uint32_t a){
    asm volatile("ldmatrix.sync.aligned.m8n8.x4.shared.b16 {%0,%1,%2,%3}, [%4];"
        : "=r"(r0),"=r"(r1),"=r"(r2),"=r"(r3) : "r"(a));
}
__device__ __forceinline__ void mma_bf(float* c, const uint32_t* a, uint32_t b0, uint32_t b1){
    asm volatile("mma.sync.aligned.m16n8k16.row.col.f32.bf16.bf16.f32 "
        "{%0,%1,%2,%3}, {%4,%5,%6,%7}, {%8,%9}, {%0,%1,%2,%3};"
        : "+f"(c[0]),"+f"(c[1]),"+f"(c[2]),"+f"(c[3])
        : "r"(a[0]),"r"(a[1]),"r"(a[2]),"r"(a[3]),"r"(b0),"r"(b1));
}
__device__ __forceinline__ void mma_fp(float* c, const uint32_t* a, uint32_t b0, uint32_t b1){
    asm volatile("mma.sync.aligned.m16n8k16.row.col.f32.f16.f16.f32 "
        "{%0,%1,%2,%3}, {%4,%5,%6,%7}, {%8,%9}, {%0,%1,%2,%3};"
        : "+f"(c[0]),"+f"(c[1]),"+f"(c[2]),"+f"(c[3])
        : "r"(a[0]),"r"(a[1]),"r"(a[2]),"r"(a[3]),"r"(b0),"r"(b1));
}
__device__ __forceinline__ void splitf(float v, bf16& h, bf16& l){
    h = __float2bfloat16(v);
    l = __float2bfloat16(v - __bfloat162float(h));
}
__device__ __forceinline__ uint32_t pack2(bf16 a, bf16 b){
    return (uint32_t)__bfloat16_as_ushort(a) | ((uint32_t)__bfloat16_as_ushort(b)<<16);
}

// ====== fp16 NT GEMM v2: 256 thr, BM=128 BN=128 BK=64, 3-stage, 2 CTA/SM ====
// warp grid 2(M) x 4(N); warp tile 64 x 32.
// mode 0: out16 = relu(acc + bias)
// mode 1: outF  = acc + bias
// mode 2: x<2 -> outF (fused, cols 0-255); x>=2 -> score epilogue (cols 256-511)
#define STV2 32768
#define SMEMV2 (3*STV2)
__global__ void __launch_bounds__(256,2) mma_fp16_v2(
    const __half* __restrict__ A, long aBatch, int ldA,
    const __half* __restrict__ B, long bBatch, int ldB, int K,
    const float* __restrict__ bias, long biasBatch,
    const float* __restrict__ addMat, int mode,
    __half* __restrict__ out16, int ld16,
    float* __restrict__ outF, long obF, int ldF,
    const float* __restrict__ wc2, float* __restrict__ scoreOut)
{
    extern __shared__ __half sm2[];
    int tid = threadIdx.x, wid = tid>>5, lane = tid&31;
    int z = blockIdx.z;
    int row0 = blockIdx.y*128, col0 = blockIdx.x*128;
    const __half* Ap = A + (size_t)z*aBatch;
    const __half* Bp = B + (size_t)z*bBatch;
    const float* biasp = bias + (size_t)z*biasBatch;
    int warpM = wid>>2, warpN = wid&3;
    float acc[4][4][4];
#pragma unroll
    for (int i=0;i<4;i++)
#pragma unroll
        for (int j=0;j<4;j++)
#pragma unroll
            for (int k=0;k<4;k++) acc[i][j][k]=0.f;

    uint32_t sb = smem_u32(sm2);
    int NK = K >> 6;

    auto load_chunk = [&](int kc, int bufi){
        uint32_t base = sb + bufi*STV2;
        int k0 = kc<<6;
#pragma unroll
        for (int it=0; it<4; it++){                 // A: 128 rows x 128B
            int idx = it*256 + tid;
            int row = idx>>3, j = idx&7;
            uint32_t dst = base + row*128 + ((j ^ (row&7))<<4);
            cp16(dst, Ap + (size_t)(row0+row)*ldA + k0 + j*8);
        }
#pragma unroll
        for (int it=0; it<4; it++){                 // B: 128 rows x 128B
            int idx = it*256 + tid;
            int row = idx>>3, j = idx&7;
            uint32_t dst = base + 16384 + row*128 + ((j ^ (row&7))<<4);
            cp16(dst, Bp + (size_t)(col0+row)*ldB + k0 + j*8);
        }
        asm volatile("cp.async.commit_group;":::"memory");
    };

    auto compute = [&](int bufi){
        uint32_t base = sb + bufi*STV2;
#pragma unroll
        for (int kk=0; kk<4; kk++){
            uint32_t ah[4][4];
#pragma unroll
            for (int mi=0;mi<4;mi++){
                int r = warpM*64 + mi*16 + (lane&15);
                int ce = kk*16 + ((lane>>4)<<3);
                uint32_t ad = base + r*128 + ((((ce>>3) ^ (r&7)))<<4);
                ldsm4(ah[mi][0],ah[mi][1],ah[mi][2],ah[mi][3], ad);
            }
#pragma unroll
            for (int np=0;np<2;np++){
                int g = lane>>3;
                int row = warpN*32 + np*16 + ((g&2)<<2) + (lane&7);
                int ce = kk*16 + ((g&1)<<3);
                uint32_t ad = base + 16384 + row*128 + ((((ce>>3) ^ (row&7)))<<4);
                uint32_t b0,b1,b2,b3;
                ldsm4(b0,b1,b2,b3, ad);
#pragma unroll
                for (int mi=0;mi<4;mi++){
                    mma_fp(acc[mi][2*np],   ah[mi], b0, b1);
                    mma_fp(acc[mi][2*np+1], ah[mi], b2, b3);
                }
            }
        }
    };

    load_chunk(0,0);
    if (NK > 1) load_chunk(1,1);
    int buf = 0;
    for (int kc=0; kc<NK; kc++){
        if (kc+1 < NK) asm volatile("cp.async.wait_group 1;":::"memory");
        else           asm volatile("cp.async.wait_group 0;":::"memory");
        __syncthreads();
        if (kc+2 < NK){
            int nb = buf+2; if (nb>=3) nb-=3;
            load_chunk(kc+2, nb);
        }
        compute(buf);
        if (++buf == 3) buf = 0;
    }

    // ---- epilogue ----
    int rb = row0 + warpM*64 + (lane>>2);
    int cb = col0 + warpN*32 + (lane&3)*2;
    bool scoreMode = (mode==2) && (blockIdx.x >= 2);
    float sacc[8];
#pragma unroll
    for (int k=0;k<8;k++) sacc[k]=0.f;
#pragma unroll
    for (int mi=0;mi<4;mi++){
        int r0 = rb + mi*16, r1 = r0 + 8;
#pragma unroll
        for (int ni=0;ni<4;ni++){
            int c = cb + ni*8;
            float b0 = biasp[c], b1 = biasp[c+1];
            float v0 = acc[mi][ni][0]+b0, v1 = acc[mi][ni][1]+b1;
            float v2 = acc[mi][ni][2]+b0, v3 = acc[mi][ni][3]+b1;
            if (scoreMode){
                int cc = c - 256;
                float2 a0 = *reinterpret_cast<const float2*>(addMat + (size_t)r0*256 + cc);
                float2 a1 = *reinterpret_cast<const float2*>(addMat + (size_t)r1*256 + cc);
                v0 = fmaxf(v0+a0.x, 0.f); v1 = fmaxf(v1+a0.y, 0.f);
                v2 = fmaxf(v2+a1.x, 0.f); v3 = fmaxf(v3+a1.y, 0.f);
                float w0 = wc2[cc], w1 = wc2[cc+1];
                sacc[mi*2+0] += v0*w0 + v1*w1;
                sacc[mi*2+1] += v2*w0 + v3*w1;
            } else if (mode==0){
                v0 = fmaxf(v0,0.f); v1 = fmaxf(v1,0.f);
                v2 = fmaxf(v2,0.f); v3 = fmaxf(v3,0.f);
                *reinterpret_cast<__half2*>(out16 + (size_t)r0*ld16 + c) = __floats2half2_rn(v0,v1);
                *reinterpret_cast<__half2*>(out16 + (size_t)r1*ld16 + c) = __floats2half2_rn(v2,v3);
            } else {
                float* o = outF + (size_t)z*obF;
                *reinterpret_cast<float2*>(o + (size_t)r0*ldF + c) = make_float2(v0,v1);
                *reinterpret_cast<float2*>(o + (size_t)r1*ldF + c) = make_float2(v2,v3);
            }
        }
    }
    if (scoreMode){
#pragma unroll
        for (int k=0;k<8;k++){
            sacc[k] += __shfl_xor_sync(0xffffffffu, sacc[k], 1);
            sacc[k] += __shfl_xor_sync(0xffffffffu, sacc[k], 2);
        }
        __syncthreads();
        float* sred = reinterpret_cast<float*>(sm2);
        if ((lane&3)==0){
#pragma unroll
            for (int k=0;k<8;k++){
                int rl = warpM*64 + (k>>1)*16 + (k&1)*8 + (lane>>2);
                sred[rl*4 + warpN] = sacc[k];
            }
        }
        __syncthreads();
        if (tid < 128){
            float p = sred[tid*4] + sred[tid*4+1] + sred[tid*4+2] + sred[tid*4+3];
            scoreOut[((size_t)z*8192 + row0 + tid)*2 + (blockIdx.x - 2)] = p;
        }
    }
}

// ================= 3-term split-bf16 NT GEMM (BK=32, 3-stage) ===============
#define ST3 32768
#define SMEM3 (3*ST3)
__global__ void __launch_bounds__(256,2) mma_gemm3(
    const bf16* __restrict__ aH, const bf16* __restrict__ aL, long aBatch, int ldA,
    const bf16* __restrict__ bH, const bf16* __restrict__ bL, long bBatch, int ldB,
    int K, float alpha, int diagMode, int zdiv,
    bf16* __restrict__ outH, bf16* __restrict__ outL,
    long obA, long obB, int ldHL,
    __half* __restrict__ outG, long obG, int ldG)
{
    extern __shared__ bf16 smem3[];
    int tid = threadIdx.x, wid = tid>>5, lane = tid&31;
    int z = blockIdx.z;
    int zq = z/zdiv, zr = z - zq*zdiv;
    float aeff = (diagMode && zq==zr) ? 0.f : alpha;
    int row0 = blockIdx.y*128, col0 = blockIdx.x*128;
    const bf16* Ah = aH + (size_t)z*aBatch;
    const bf16* Al = aL + (size_t)z*aBatch;
    const bf16* Bh = bH + (size_t)z*bBatch;
    const bf16* Bl = bL + (size_t)z*bBatch;

    int warpM = wid>>1, warpN = wid&1;
    float acc[2][8][4];
#pragma unroll
    for (int i=0;i<2;i++)
#pragma unroll
        for (int j=0;j<8;j++)
#pragma unroll
            for (int k=0;k<4;k++) acc[i][j][k]=0.f;

    uint32_t sb = smem_u32(smem3);
    int NK = K >> 5;

    auto load_chunk = [&](int kc, int bufi){
        uint32_t base = sb + bufi*ST3;
        int k0 = kc<<5;
#pragma unroll
        for (int arr=0; arr<4; arr++){
            const bf16* g = (arr==0)?Ah:(arr==1)?Al:(arr==2)?Bh:Bl;
            int ld = (arr<2)?ldA:ldB;
            int r0g = (arr<2)?row0:col0;
#pragma unroll
            for (int part=0; part<2; part++){
                int idx = part*256 + tid;
                int row = idx>>2, j = idx&3;
                uint32_t dst = base + arr*8192 + row*64 + (((j ^ (row>>1)) & 3)<<4);
                cp16(dst, g + (size_t)(r0g+row)*ld + k0 + j*8);
            }
        }
        asm volatile("cp.async.commit_group;":::"memory");
    };

    auto compute = [&](int bufi){
        uint32_t base = sb + bufi*ST3;
#pragma unroll
        for (int kk=0; kk<2; kk++){
            uint32_t ah[2][4], al[2][4];
#pragma unroll
            for (int mi=0;mi<2;mi++){
                int r = warpM*32 + mi*16 + (lane&15);
                int c = kk*16 + ((lane>>4)<<3);
                uint32_t ad = base + r*64 + ((((c>>3) ^ (r>>1)) & 3)<<4);
                ldsm4(ah[mi][0],ah[mi][1],ah[mi][2],ah[mi][3], ad);
                ldsm4(al[mi][0],al[mi][1],al[mi][2],al[mi][3], ad + 8192);
            }
#pragma unroll
            for (int np=0;np<4;np++){
                int g = lane>>3;
                int row = warpN*64 + np*16 + ((g&2)<<2) + (lane&7);
                int c = kk*16 + ((g&1)<<3);
                uint32_t ad = base + 16384 + row*64 + ((((c>>3) ^ (row>>1)) & 3)<<4);
                uint32_t bh0,bh1,bh2,bh3, bl0,bl1,bl2,bl3;
                ldsm4(bh0,bh1,bh2,bh3, ad);
                ldsm4(bl0,bl1,bl2,bl3, ad + 8192);
#pragma unroll
                for (int mi=0;mi<2;mi++){
                    mma_bf(acc[mi][2*np],   ah[mi], bh0, bh1);
                    mma_bf(acc[mi][2*np],   al[mi], bh0, bh1);
                    mma_bf(acc[mi][2*np],   ah[mi], bl0, bl1);
                    mma_bf(acc[mi][2*np+1], ah[mi], bh2, bh3);
                    mma_bf(acc[mi][2*np+1], al[mi], bh2, bh3);
                    mma_bf(acc[mi][2*np+1], ah[mi], bl2, bl3);
                }
            }
        }
    };

    load_chunk(0,0);
    load_chunk(1,1);
    int buf = 0;
    for (int kc=0; kc<NK; kc++){
        if (kc+1 < NK) asm volatile("cp.async.wait_group 1;":::"memory");
        else           asm volatile("cp.async.wait_group 0;":::"memory");
        __syncthreads();
        if (kc+2 < NK){
            int nb = buf+2; if (nb>=3) nb-=3;
            load_chunk(kc+2, nb);
        }
        compute(buf);
        if (++buf == 3) buf = 0;
    }

    int rb = row0 + warpM*32 + (lane>>2);
    int cb = col0 + warpN*64 + (lane&3)*2;
#pragma unroll
    for (int mi=0;mi<2;mi++){
        int r0 = rb + mi*16, r1 = r0 + 8;
#pragma unroll
        for (int ni=0;ni<8;ni++){
            int c = cb + ni*8;
            float v[4];
#pragma unroll
            for (int k=0;k<4;k++) v[k] = acc[mi][ni][k]*aeff;
            if (outH){
                size_t ob = (size_t)zq*obA + (size_t)zr*obB + c;
                bf16 h0,l0,h1,l1;
                splitf(v[0],h0,l0); splitf(v[1],h1,l1);
                *reinterpret_cast<uint32_t*>(outH + ob + (size_t)r0*ldHL) = pack2(h0,h1);
                *reinterpret_cast<uint32_t*>(outL + ob + (size_t)r0*ldHL) = pack2(l0,l1);
                splitf(v[2],h0,l0); splitf(v[3],h1,l1);
                *reinterpret_cast<uint32_t*>(outH + ob + (size_t)r1*ldHL) = pack2(h0,h1);
                *reinterpret_cast<uint32_t*>(outL + ob + (size_t)r1*ldHL) = pack2(l0,l1);
            }
            if (outG){
                size_t og = (size_t)z*obG + c;
                *reinterpret_cast<__half2*>(outG + og + (size_t)r0*ldG) = __floats2half2_rn(v[0],v[1]);
                *reinterpret_cast<__half2*>(outG + og + (size_t)r1*ldG) = __floats2half2_rn(v[2],v[3]);
            }
        }
    }
}

// ---------------- prep kernels ----------------------------------------------
__global__ void conv_fp16(const float* __restrict__ s, __half* __restrict__ d, int n){
    int i = blockIdx.x*256 + threadIdx.x;
    if (i < n) d[i] = __float2half(s[i]);
}
__global__ void transpose_split(const float* __restrict__ S, bf16* __restrict__ TH, bf16* __restrict__ TL){
    __shared__ float tile[32][33];
    int p = blockIdx.z;
    const float* src = S + (size_t)p*65536;
    int x0 = blockIdx.x*32, y0 = blockIdx.y*32;
    for (int j = threadIdx.y; j < 32; j += 8)
        tile[j][threadIdx.x] = src[(size_t)(y0+j)*256 + x0 + threadIdx.x];
    __syncthreads();
    for (int j = threadIdx.y; j < 32; j += 8) {
        float v = tile[threadIdx.x][j];
        bf16 h, l; splitf(v, h, l);
        size_t o = (size_t)p*65536 + (size_t)(x0+j)*256 + y0 + threadIdx.x;
        TH[o] = h; TL[o] = l;
    }
}
__global__ void split_arr(const float* __restrict__ s, bf16* __restrict__ H, bf16* __restrict__ L, int n){
    int i = blockIdx.x*256 + threadIdx.x;
    if (i < n) { bf16 h, l; splitf(s[i], h, l); H[i] = h; L[i] = l; }
}
__global__ void xcat_fp16(const float* __restrict__ x, __half* __restrict__ Xh){
    size_t i = (size_t)blockIdx.x*256 + threadIdx.x;   // 4,194,304 float4 units
    int d4 = (int)(i & 63); size_t r = i >> 6;
    int b = (int)(r & 8191); int t = (int)(r >> 13);
    float4 v = reinterpret_cast<const float4*>(x)[i];
    size_t o = ((size_t)b*2048 + t*256 + d4*4) >> 1;
    reinterpret_cast<__half2*>(Xh)[o]   = __floats2half2_rn(v.x, v.y);
    reinterpret_cast<__half2*>(Xh)[o+1] = __floats2half2_rn(v.z, v.w);
}
__global__ void cbias_bias1p(const float* __restrict__ Wo, const float* __restrict__ bv,
                             const float* __restrict__ bo, const float* __restrict__ W1,
                             const float* __restrict__ b1, float* __restrict__ bias1p){
    int m = blockIdx.x;
    int w = threadIdx.x>>5, lane = threadIdx.x&31;
    __shared__ float cb[256];
    for (int r=0;r<32;r++){
        int o = w*32 + r;
        float p = 0.f;
        for (int t=0;t<8;t++){
            if (t==m) continue;
            size_t zz = (size_t)(m*8 + t);
            const float* W = Wo + zz*65536 + (size_t)o*256;
            const float* bvp = bv + zz*256;
            float q = 0.f;
#pragma unroll
            for (int j=0;j<8;j++) q += W[lane + j*32]*bvp[lane + j*32];
            p += q;
        }
#pragma unroll
        for (int off=16; off; off>>=1) p += __shfl_xor_sync(0xffffffffu, p, off);
        if (lane==0){
            float bs = 0.f;
            for (int t=0;t<8;t++) if (t!=m) bs += bo[(m*8+t)*256 + o];
            cb[o] = (p + bs) * (1.f/7.f);
        }
    }
    __syncthreads();
    for (int r=0;r<32;r++){
        int h = w*32 + r;
        float p = 0.f;
#pragma unroll
        for (int j=0;j<8;j++)
            p += W1[(size_t)m*131072 + (size_t)h*512 + 256 + lane + j*32] * cb[lane + j*32];
#pragma unroll
        for (int off=16; off; off>>=1) p += __shfl_xor_sync(0xffffffffu, p, off);
        if (lane==0) bias1p[m*256 + h] = p + b1[m*256 + h];
    }
}
__global__ void w2_to_b2_fp16(const float* __restrict__ W2, __half* __restrict__ B2h){
    int i = blockIdx.x*256 + threadIdx.x;       // 524288
    int m = i>>16, rem = i&65535;
    B2h[(size_t)m*131072 + rem] = __float2half(W2[i]);
}
__global__ void biasF_bias2c(const float* __restrict__ Wc1, const float* __restrict__ b2,
                             float* __restrict__ bias2c){
    int m = blockIdx.x;
    int w = threadIdx.x>>5, lane = threadIdx.x&31;
    __shared__ float bf[256];
    for (int r=0;r<32;r++){
        int d = w*32 + r;
        float p = 0.f;
#pragma unroll
        for (int j=0;j<8;j++)
            p += Wc1[(size_t)d*512 + 256 + lane + j*32] * b2[m*256 + lane + j*32];
#pragma unroll
        for (int off=16; off; off>>=1) p += __shfl_xor_sync(0xffffffffu, p, off);
        if (lane==0) bf[d] = p;
    }
    __syncthreads();
    bias2c[m*512 + threadIdx.x] = b2[m*256 + threadIdx.x];
    bias2c[m*512 + 256 + threadIdx.x] = bf[threadIdx.x];
}
__global__ void g_patch_fp16(const float* __restrict__ W1, __half* __restrict__ Gh){
    int i = blockIdx.x*256 + threadIdx.x;       // 524288
    int m = i>>16, rem = i&65535, h = rem>>8, d = rem&255;
    Gh[(size_t)m*524288 + (size_t)h*2048 + m*256 + d] =
        __float2half(W1[(size_t)m*131072 + (size_t)h*512 + d]);
}
__global__ void final_gate(const float* __restrict__ scorep, const float* __restrict__ fused,
                           const float* __restrict__ bc2, float* __restrict__ out){
    int b = blockIdx.x, tid = threadIdx.x;
    __shared__ float ssc[8];
    if (tid < 8){
        size_t i = ((size_t)tid*8192 + b)*2;
        float p = scorep[i] + scorep[i+1];
        ssc[tid] = 1.f/(1.f + expf(-(p + bc2[0])));
    }
    __syncthreads();
    float a = 0.f;
#pragma unroll
    for (int m=0;m<8;m++)
        a += ssc[m]*fused[((size_t)m*8192 + b)*256 + tid];
    out[(size_t)b*256 + tid] = a*0.125f;
}

// ---------------- launch ----------------------------------------------------
extern "C" void kernel_launch(void* const* d_in, const int* in_sizes, int n_in,
                              void* d_out, int out_size) {
    const float* x   = (const float*)d_in[0];
    const float* rq  = (const float*)d_in[1];
    const float* Wv  = (const float*)d_in[2];
    const float* bv  = (const float*)d_in[3];
    const float* Wo  = (const float*)d_in[4];
    const float* bo  = (const float*)d_in[5];
    const float* W1  = (const float*)d_in[6];
    const float* b1  = (const float*)d_in[7];
    const float* W2  = (const float*)d_in[8];
    const float* b2  = (const float*)d_in[9];
    const float* Wc1 = (const float*)d_in[10];
    const float* bc1 = (const float*)d_in[11];
    const float* wc2 = (const float*)d_in[12];
    const float* bc2 = (const float*)d_in[13];
    float* out = (float*)d_out;

    __half *pXh,*pGh,*pHh,*pB2h,*pRqh,*pWc1h;
    bf16 *pWoH,*pWoL,*pWvH,*pWvL,*pEfH,*pEfL,*pW1H,*pW1L,*pW2TH,*pW2TL,*pWcH,*pWcL;
    float *pfused,*pqpart,*pbias1p,*pbias2c,*pscorep;
    cudaGetSymbolAddress((void**)&pXh, g_Xh);      cudaGetSymbolAddress((void**)&pGh, g_Gh);
    cudaGetSymbolAddress((void**)&pHh, g_Hidh);    cudaGetSymbolAddress((void**)&pB2h, g_B2h);
    cudaGetSymbolAddress((void**)&pRqh, g_Rqh);    cudaGetSymbolAddress((void**)&pWc1h, g_Wc1h);
    cudaGetSymbolAddress((void**)&pWoH, g_WoH);    cudaGetSymbolAddress((void**)&pWoL, g_WoL);
    cudaGetSymbolAddress((void**)&pWvH, g_WvTH);   cudaGetSymbolAddress((void**)&pWvL, g_WvTL);
    cudaGetSymbolAddress((void**)&pEfH, g_EfTH);   cudaGetSymbolAddress((void**)&pEfL, g_EfTL);
    cudaGetSymbolAddress((void**)&pW1H, g_W1H);    cudaGetSymbolAddress((void**)&pW1L, g_W1L);
    cudaGetSymbolAddress((void**)&pW2TH, g_W2TH);  cudaGetSymbolAddress((void**)&pW2TL, g_W2TL);
    cudaGetSymbolAddress((void**)&pWcH, g_WcH);    cudaGetSymbolAddress((void**)&pWcL, g_WcL);
    cudaGetSymbolAddress((void**)&pfused, g_fused);
    cudaGetSymbolAddress((void**)&pqpart, g_qpart);
    cudaGetSymbolAddress((void**)&pbias1p, g_bias1p);
    cudaGetSymbolAddress((void**)&pbias2c, g_bias2c);
    cudaGetSymbolAddress((void**)&pscorep, g_scorep);
    cudaFuncSetAttribute(mma_gemm3,   cudaFuncAttributeMaxDynamicSharedMemorySize, SMEM3);
    cudaFuncSetAttribute(mma_fp16_v2, cudaFuncAttributeMaxDynamicSharedMemorySize, SMEMV2);

    // side stream + events (created once; per-call work identical)
    static cudaStream_t sB = nullptr;
    static cudaEvent_t eFork = nullptr, eB1 = nullptr, eB2 = nullptr;
    if (!sB){
        cudaStreamCreateWithFlags(&sB, cudaStreamNonBlocking);
        cudaEventCreateWithFlags(&eFork, cudaEventDisableTiming);
        cudaEventCreateWithFlags(&eB1, cudaEventDisableTiming);
        cudaEventCreateWithFlags(&eB2, cudaEventDisableTiming);
    }

    // ---- fork ----
    cudaEventRecord(eFork, 0);
    cudaStreamWaitEvent(sB, eFork, 0);

    // ---- branch B (independent of E/G chain) ----
    xcat_fp16<<<16384, 256, 0, sB>>>(x, pXh);
    cbias_bias1p<<<8, 256, 0, sB>>>(Wo, bv, bo, W1, b1, pbias1p);
    cudaEventRecord(eB1, sB);                       // hid needs Xh + bias1p
    conv_fp16<<<8192, 256, 0, sB>>>(rq, pRqh, 2097152);
    conv_fp16<<<512, 256, 0, sB>>>(Wc1, pWc1h, 131072);
    mma_fp16_v2<<<dim3(2,64,1), 256, SMEMV2, sB>>>( // qpart
        pRqh, 0, 256,  pWc1h, 0, 512,  256,
        bc1, 0,  nullptr, 1,
        nullptr, 0,
        pqpart, 0, 256,
        nullptr, nullptr);
    transpose_split<<<dim3(8,8,8), dim3(32,8), 0, sB>>>(W2, pW2TH, pW2TL);
    split_arr<<<512, 256, 0, sB>>>(Wc1, pWcH, pWcL, 131072);
    w2_to_b2_fp16<<<2048, 256, 0, sB>>>(W2, pB2h);
    biasF_bias2c<<<8, 256, 0, sB>>>(Wc1, b2, pbias2c);
    mma_gemm3<<<dim3(2,2,8), 256, SMEM3, sB>>>(     // F-build -> B2 rows 256-511
        pWcH+256, pWcL+256, 0, 512,  pW2TH, pW2TL, 65536, 256,  256,
        1.f, 0, 1,
        nullptr, nullptr, 0, 0, 0,
        pB2h+65536, 131072, 256);
    cudaEventRecord(eB2, sB);                       // fused/score needs all of B

    // ---- main chain (stream 0): E -> G -> hid -> fused -> gate ----
    transpose_split<<<dim3(8,8,64), dim3(32,8)>>>(Wv, pWvH, pWvL);
    split_arr<<<16384, 256>>>(Wo, pWoH, pWoL, 4194304);
    split_arr<<<4096, 256>>>(W1, pW1H, pW1L, 1048576);
    // EfT[s][(t,d)][o] = (s!=t)/7 * sum_e WvT[s,t][d,e]*Wo[s,t][o,e]
    mma_gemm3<<<dim3(2,2,64), 256, SMEM3>>>(
        pWvH, pWvL, 65536, 256,  pWoH, pWoL, 65536, 256,  256,
        1.f/7.f, 1, 8,
        pEfH, pEfL, 524288, 65536, 256,
        nullptr, 0, 0);
    // G[m][h][td] = sum_o W1c[m][h,o]*EfT[m][(td)][o]  -> fp16
    mma_gemm3<<<dim3(16,2,8), 256, SMEM3>>>(
        pW1H+256, pW1L+256, 131072, 512,  pEfH, pEfL, 524288, 256,  256,
        1.f, 0, 1,
        nullptr, nullptr, 0, 0, 0,
        pGh, 524288, 2048);
    g_patch_fp16<<<2048, 256>>>(W1, pGh);
    cudaStreamWaitEvent(0, eB1, 0);
    // hid_all = relu(Xh @ Gh^T + bias1p)  [8192x2048, K=2048] -> fp16
    mma_fp16_v2<<<dim3(16,64,1), 256, SMEMV2>>>(
        pXh, 0, 2048,  pGh, 0, 2048,  2048,
        pbias1p, 0,  nullptr, 0,
        pHh, 2048,
        nullptr, 0, 0,
        nullptr, nullptr);
    cudaStreamWaitEvent(0, eB2, 0);
    // fused (x=0,1 -> fp32 cols 0-255) + score (x=2,3 -> slots 0,1)
    mma_fp16_v2<<<dim3(4,64,8), 256, SMEMV2>>>(
        pHh, 256, 2048,  pB2h, 131072, 256,  256,
        pbias2c, 512,  pqpart, 2,
        nullptr, 0,
        pfused, 2097152, 256,
        wc2, pscorep);
    final_gate<<<8192, 256>>>(pscorep, pfused, bc2, out);
}